// round 12
// baseline (speedup 1.0000x reference)
#include <cuda_runtime.h>

// RFCM loss — fused single kernel, v11: v10 + software-pipelined loads
// (prefetch z+2 after the barrier, covered by the consume phase; zero extra regs).
// J1 = (1/N)*sum_{b,k}(C - A^2/B); A=sum(mem*img), B=sum(mem), C=sum(mem*img^2)
// J2 = 2*sum_{k<k'} [ <Bx(mem_k), ByBz(mem_k')> - <mem_k, mem_k'> ]
// mem = y_pred^2, zero-padded 3x3x3 box stencil.

#define FULLMASK 0xffffffffu

__device__ double g_acc[25];
__device__ unsigned int g_sem;

__device__ __forceinline__ float4 sq4(float4 p) {
    float4 m; m.x=p.x*p.x; m.y=p.y*p.y; m.z=p.z*p.z; m.w=p.w*p.w; return m;
}
__device__ __forceinline__ float4 add4(float4 a, float4 b) {
    float4 r; r.x=a.x+b.x; r.y=a.y+b.y; r.z=a.z+b.z; r.w=a.w+b.w; return r;
}

// smem (float4): s_zs [slot2][k4][row10][32], s_ex [slot2][ty8][32], s_hr [3][8][32], s_red
#define ZS_F4 (2*4*10*32)
#define EX_F4 (2*8*32)
#define HR_F4 (3*8*32)
#define SLOT_F4 (4*10*32)     // 1280
#define SMEM_BYTES ((ZS_F4 + EX_F4 + HR_F4)*16 + 16*8*4)

__global__ __launch_bounds__(512, 2)
void rfcm_kernel(const float* __restrict__ ypred, const float* __restrict__ image,
                 float* __restrict__ out) {
    extern __shared__ float4 smem4[];
    float4* s_zs = smem4;                       // ((slot*4+k)*10+row)*32+tx
    float4* s_ex = smem4 + ZS_F4;               // (slot*8+ty)*32+tx
    float4* s_hr = smem4 + ZS_F4 + EX_F4;       // (hslot*8+hid)*32+tx (thread-private)
    float*  s_red = (float*)(smem4 + ZS_F4 + EX_F4 + HR_F4);

    const int tx = threadIdx.x;
    const int ty = threadIdx.y;                 // y row 0..7
    const int tk = threadIdx.z;                 // k group: ks = 2tk, 2tk+1
    const int tid = tx + 32*ty + 256*tk;
    const int wid = ty + 8*tk;
    const int y0 = blockIdx.x * 8;
    const int z0 = blockIdx.y * 16;
    const int b  = blockIdx.z;
    const int gy = y0 + ty;
    const int ks = 2*tk;

    // halo tasks: warps ty<4 per group own (hk = 2tk+(ty&1), side = ty>>1)
    const bool haloW = (ty < 4);
    const int hk = ks + (ty & 1);
    const int hy = (ty >> 1) ? (y0 + 8) : (y0 - 1);
    const int hr = (ty >> 1) ? 9 : 0;
    const int hid = tk*4 + ty;
    const bool hyOK = (unsigned)hy < 128u;

    const float* yp_b = ypred + (size_t)b * 4 * 128 * 16384;
    const float* im_b = image + (size_t)b * 128 * 16384;

    auto ldsq = [&](int k, int zz, int yy) -> float4 {   // prologue-only path
        float4 p = make_float4(0.f,0.f,0.f,0.f);
        if ((unsigned)zz < 128u && (unsigned)yy < 128u)
            p = *(const float4*)(yp_b + (((size_t)(k*128+zz))<<14) + (yy<<7) + (tx<<2));
        return sq4(p);
    };
    auto xsum = [&](float4 m) -> float4 {
        float lf = __shfl_up_sync(FULLMASK, m.w, 1);
        float rt = __shfl_down_sync(FULLMASK, m.x, 1);
        if (tx == 0)  lf = 0.f;
        if (tx == 31) rt = 0.f;
        float4 r;
        r.x = lf  + m.x + m.y;
        r.y = m.x + m.y + m.z;
        r.z = m.y + m.z + m.w;
        r.w = m.z + m.w + rt;
        return r;
    };

    // streaming pointers, starting at plane z0+2 (first in-loop prefetch target)
    const float4* pOwn0 = (const float4*)(yp_b + (((size_t)(ks*128 + z0 + 2))<<14) + (gy<<7) + (tx<<2));
    const float4* pOwn1 = (const float4*)(yp_b + (((size_t)((ks+1)*128 + z0 + 2))<<14) + (gy<<7) + (tx<<2));
    const float4* pImg  = (const float4*)(im_b + (((size_t)z0)<<14) + (gy<<7) + (tx<<2));
    const float4* pHal  = (const float4*)(yp_b + (((size_t)(hk*128 + z0 + 2))<<14) + ((hy & 127)<<7) + (tx<<2));

    // smem base pointers (slot 0); per-parity offset = slot*SLOT_F4
    float4* zOwnS0 = &s_zs[((ks    )*10 + ty + 1)*32 + tx];
    float4* zOwnS1 = &s_zs[((ks + 1)*10 + ty + 1)*32 + tx];
    float4* zHalS  = &s_zs[(hk*10 + hr)*32 + tx];
    const float4* zLoc  = &s_zs[((ks + 1)*10 + ty)*32 + tx];
    const int ko = 2*(tk ^ 1);
    const float4* zOth0 = &s_zs[((ko    )*10 + ty)*32 + tx];
    const float4* zOth1 = &s_zs[((ko + 1)*10 + ty)*32 + tx];
    float4* exMine = &s_ex[ty*32 + tx];
    float4* hRing  = &s_hr[hid*32 + tx];

    // prologue: window m0=m(z0-1), m1=m(z0), m2=m(z0+1); ring holds those 3 halos
    float4 m0[2], m1[2], m2[2];
    m0[0] = ldsq(ks,   z0 - 1, gy);
    m0[1] = ldsq(ks+1, z0 - 1, gy);
    m1[0] = ldsq(ks,   z0,     gy);
    m1[1] = ldsq(ks+1, z0,     gy);
    m2[0] = ldsq(ks,   z0 + 1, gy);
    m2[1] = ldsq(ks+1, z0 + 1, gy);
    if (haloW) {
        hRing[((z0 + 2) % 3) * 256] = ldsq(hk, z0 - 1, hy);
        hRing[((z0    ) % 3) * 256] = ldsq(hk, z0,     hy);
        hRing[((z0 + 1) % 3) * 256] = ldsq(hk, z0 + 1, hy);
    }

    float accB[2] = {0,0}, accA[2] = {0,0}, accC[2] = {0,0};
    float j2 = 0.f;

    for (int zi = 0; zi < 16; zi++) {
        const int z = z0 + zi;
        const int slot = z & 1;
        const int so = slot * SLOT_F4;

        // ---- build plane z (window fully resident: no stalls) ----
        float4 zs1;
        zOwnS0[so] = add4(add4(m0[0], m1[0]), m2[0]);
        zs1 = add4(add4(m0[1], m1[1]), m2[1]);
        zOwnS1[so] = zs1;
        if (haloW)
            zHalS[so] = add4(add4(hRing[0], hRing[256]), hRing[512]);
        if (tk != slot)
            exMine[slot * 256] = add4(m1[0], m1[1]);
        const float4 img = *pImg; pImg += 4096;   // issued pre-barrier, used post
        __syncthreads();

        // ---- rotate window, then prefetch plane z+2 (covered by consume) ----
        m0[0] = m1[0]; m0[1] = m1[1];             // m0 := m(z)  (center for consume)
        m1[0] = m2[0]; m1[1] = m2[1];             // m1 := m(z+1)
        const bool pf = (zi < 15);
        const bool zOK = pf & (z + 2 < 128);
        float4 hv = make_float4(0.f,0.f,0.f,0.f);
        if (zOK) { m2[0] = sq4(*pOwn0); m2[1] = sq4(*pOwn1); }
        else     { m2[0] = make_float4(0.f,0.f,0.f,0.f); m2[1] = m2[0]; }
        pOwn0 += 4096; pOwn1 += 4096;
        if (haloW) { if (zOK & hyOK) hv = sq4(*pHal); pHal += 4096; }

        // ---- consume plane z (center = m0) ----
        float4 jv;
        #pragma unroll
        for (int j = 0; j < 2; j++) {
            const float4 mc = m0[j];
            accB[j] += (mc.x + mc.y) + (mc.z + mc.w);
            float tX = mc.x*img.x, tY = mc.y*img.y, tZ = mc.z*img.z, tW = mc.w*img.w;
            accA[j] += (tX + tY) + (tZ + tW);
            accC[j] += fmaf(tX, img.x, fmaf(tY, img.y, fmaf(tZ, img.z, tW*img.w)));
        }
        const float4 a0 = xsum(m0[0]);
        {
            float4 b1 = add4(add4(zLoc[so], zs1), zLoc[so + 64]);
            jv.x = fmaf(a0.x, b1.x, -m0[0].x * m0[1].x);
            jv.y = fmaf(a0.y, b1.y, -m0[0].y * m0[1].y);
            jv.z = fmaf(a0.z, b1.z, -m0[0].z * m0[1].z);
            jv.w = fmaf(a0.w, b1.w, -m0[0].w * m0[1].w);
        }
        if (tk == slot) {
            float4 bO = add4(add4(add4(zOth0[so], zOth1[so]),
                                  add4(zOth0[so + 32], zOth1[so + 32])),
                             add4(zOth0[so + 64], zOth1[so + 64]));
            float4 aS = add4(a0, xsum(m0[1]));
            float4 cS = add4(m0[0], m0[1]);
            float4 cO = s_ex[slot*256 + ty*32 + tx];
            jv.x = fmaf(aS.x, bO.x, fmaf(-cS.x, cO.x, jv.x));
            jv.y = fmaf(aS.y, bO.y, fmaf(-cS.y, cO.y, jv.y));
            jv.z = fmaf(aS.z, bO.z, fmaf(-cS.z, cO.z, jv.z));
            jv.w = fmaf(aS.w, bO.w, fmaf(-cS.w, cO.w, jv.w));
        }
        j2 += (jv.x + jv.y) + (jv.z + jv.w);

        // ring update LAST: hv's LDG latency covered by the consume math above.
        // (thread-private smem; the overwritten slot held z-1, now dead)
        if (haloW & pf)
            hRing[((z + 2) % 3) * 256] = hv;
    }

    // ---- reduction (J2 carries symmetry factor 2) ----
    float vals[7] = { accB[0], accB[1], accA[0], accA[1], accC[0], accC[1], 2.f * j2 };
    #pragma unroll
    for (int q = 0; q < 7; q++) {
        float v = vals[q];
        #pragma unroll
        for (int off = 16; off; off >>= 1) v += __shfl_xor_sync(FULLMASK, v, off);
        vals[q] = v;
    }
    __syncthreads();
    if (tx == 0) {
        #pragma unroll
        for (int q = 0; q < 7; q++) s_red[wid*8 + q] = vals[q];
    }
    __syncthreads();
    if (tid < 14) {
        const int g = tid / 7, q = tid % 7;
        float s = 0.f;
        #pragma unroll
        for (int w = 0; w < 8; w++) s += s_red[(8*g + w)*8 + q];
        double* dst;
        if (q < 2)       dst = &g_acc[b*4 + 2*g + q];
        else if (q < 4)  dst = &g_acc[8 + b*4 + 2*g + (q - 2)];
        else if (q < 6)  dst = &g_acc[16 + b*4 + 2*g + (q - 4)];
        else             dst = &g_acc[24];
        atomicAdd(dst, (double)s);
        __threadfence();
    }
    __syncthreads();

    // ---- last of 256 blocks finalizes + resets for next graph replay ----
    if (tid == 0) {
        unsigned old = atomicAdd(&g_sem, 1u);
        if (old == 255u) {
            volatile double* ga = g_acc;
            double j1 = 0.0;
            #pragma unroll
            for (int i = 0; i < 8; i++) {
                double Bv = ga[i], Av = ga[8 + i], Cv = ga[16 + i];
                j1 += Cv - Av * Av / Bv;
            }
            const double inv = 1.0 / 4194304.0;
            out[0] = (float)(j1 * inv + 0.0008 * ga[24] * inv);
            #pragma unroll
            for (int i = 0; i < 25; i++) g_acc[i] = 0.0;
            g_sem = 0u;
        }
    }
}

extern "C" void kernel_launch(void* const* d_in, const int* in_sizes, int n_in,
                              void* d_out, int out_size) {
    const float* ypred = (const float*)d_in[0];
    const float* image = (const float*)d_in[1];
    if (n_in >= 2 && in_sizes[0] < in_sizes[1]) {  // robustness to input order
        ypred = (const float*)d_in[1];
        image = (const float*)d_in[0];
    }
    cudaFuncSetAttribute(rfcm_kernel, cudaFuncAttributeMaxDynamicSharedMemorySize,
                         SMEM_BYTES);
    rfcm_kernel<<<dim3(16, 8, 2), dim3(32, 8, 2), SMEM_BYTES>>>(ypred, image, (float*)d_out);
}

// round 13
// speedup vs baseline: 1.1923x; 1.1923x over previous
#include <cuda_runtime.h>

// RFCM loss — fused single kernel, v12: v10 structure at 256 threads
// (32x4x2), 4 blocks/SM -> 4 independent barrier domains hide latency.
// J1 = (1/N)*sum_{b,k}(C - A^2/B); A=sum(mem*img), B=sum(mem), C=sum(mem*img^2)
// J2 = 2*sum_{k<k'} [ <Bx(mem_k), ByBz(mem_k')> - <mem_k, mem_k'> ]
// mem = y_pred^2, zero-padded 3x3x3 box stencil.

#define FULLMASK 0xffffffffu

__device__ double g_acc[25];
__device__ unsigned int g_sem;

__device__ __forceinline__ float4 sq4(float4 p) {
    float4 m; m.x=p.x*p.x; m.y=p.y*p.y; m.z=p.z*p.z; m.w=p.w*p.w; return m;
}
__device__ __forceinline__ float4 add4(float4 a, float4 b) {
    float4 r; r.x=a.x+b.x; r.y=a.y+b.y; r.z=a.z+b.z; r.w=a.w+b.w; return r;
}

// smem (float4): s_zs [slot2][k4][row6][32], s_ex [slot2][ty4][32], s_hr [3][8][32], s_red
#define ZS_F4 (2*4*6*32)
#define EX_F4 (2*4*32)
#define HR_F4 (3*8*32)
#define SLOT_F4 (4*6*32)      // 768
#define SMEM_BYTES ((ZS_F4 + EX_F4 + HR_F4)*16 + 8*8*4)

__global__ __launch_bounds__(256, 4)
void rfcm_kernel(const float* __restrict__ ypred, const float* __restrict__ image,
                 float* __restrict__ out) {
    extern __shared__ float4 smem4[];
    float4* s_zs = smem4;                       // ((slot*4+k)*6+row)*32+tx
    float4* s_ex = smem4 + ZS_F4;               // (slot*4+ty)*32+tx
    float4* s_hr = smem4 + ZS_F4 + EX_F4;       // (hslot*8+hid)*32+tx
    float*  s_red = (float*)(smem4 + ZS_F4 + EX_F4 + HR_F4);

    const int tx = threadIdx.x;
    const int ty = threadIdx.y;                 // y row 0..3
    const int tk = threadIdx.z;                 // k group: ks = 2tk, 2tk+1
    const int tid = tx + 32*ty + 128*tk;
    const int wid = ty + 4*tk;                  // warp id 0..7
    const int y0 = blockIdx.x * 4;
    const int z0 = blockIdx.y * 16;
    const int b  = blockIdx.z;
    const int gy = y0 + ty;
    const int ks = 2*tk;

    // halo: 8 tasks on 8 warps: hk = 2tk+(ty&1), side = ty>>1
    const int hk = ks + (ty & 1);
    const int hy = (ty >> 1) ? (y0 + 4) : (y0 - 1);
    const int hr = (ty >> 1) ? 5 : 0;
    const int hid = tk*4 + ty;                  // 0..7
    const bool hyOK = (unsigned)hy < 128u;

    const float* yp_b = ypred + (size_t)b * 4 * 128 * 16384;
    const float* im_b = image + (size_t)b * 128 * 16384;

    auto ldsq = [&](int k, int zz, int yy) -> float4 {   // prologue-only path
        float4 p = make_float4(0.f,0.f,0.f,0.f);
        if ((unsigned)zz < 128u && (unsigned)yy < 128u)
            p = *(const float4*)(yp_b + (((size_t)(k*128+zz))<<14) + (yy<<7) + (tx<<2));
        return sq4(p);
    };
    auto xsum = [&](float4 m) -> float4 {
        float lf = __shfl_up_sync(FULLMASK, m.w, 1);
        float rt = __shfl_down_sync(FULLMASK, m.x, 1);
        if (tx == 0)  lf = 0.f;
        if (tx == 31) rt = 0.f;
        float4 r;
        r.x = lf  + m.x + m.y;
        r.y = m.x + m.y + m.z;
        r.z = m.y + m.z + m.w;
        r.w = m.z + m.w + rt;
        return r;
    };

    // streaming pointers (advance 4096 float4 = one z-plane per iteration)
    const float4* pOwn0 = (const float4*)(yp_b + (((size_t)(ks*128 + z0 + 1))<<14) + (gy<<7) + (tx<<2));
    const float4* pOwn1 = (const float4*)(yp_b + (((size_t)((ks+1)*128 + z0 + 1))<<14) + (gy<<7) + (tx<<2));
    const float4* pImg  = (const float4*)(im_b + (((size_t)z0)<<14) + (gy<<7) + (tx<<2));
    const float4* pHal  = (const float4*)(yp_b + (((size_t)(hk*128 + z0 + 1))<<14) + ((hy & 127)<<7) + (tx<<2));

    // smem base pointers (slot 0); per-parity offset = slot*SLOT_F4
    float4* zOwnS0 = &s_zs[((ks    )*6 + ty + 1)*32 + tx];
    float4* zOwnS1 = &s_zs[((ks + 1)*6 + ty + 1)*32 + tx];
    float4* zHalS  = &s_zs[(hk*6 + hr)*32 + tx];
    const float4* zLoc  = &s_zs[((ks + 1)*6 + ty)*32 + tx];
    const int ko = 2*(tk ^ 1);
    const float4* zOth0 = &s_zs[((ko    )*6 + ty)*32 + tx];
    const float4* zOth1 = &s_zs[((ko + 1)*6 + ty)*32 + tx];
    float4* exMine = &s_ex[ty*32 + tx];                           // + slot*128
    float4* hRing  = &s_hr[hid*32 + tx];                          // + hslot*256

    // rolling raw window m0=m(z-1), m1=m(z)
    float4 m0[2], m1[2], m2[2];
    m0[0] = ldsq(ks,   z0 - 1, gy);
    m0[1] = ldsq(ks+1, z0 - 1, gy);
    m1[0] = ldsq(ks,   z0,     gy);
    m1[1] = ldsq(ks+1, z0,     gy);
    // prologue halo ring: zz=z0-1 -> slot (z0)%3, zz=z0 -> slot (z0+1)%3
    hRing[((z0    ) % 3) * 256] = ldsq(hk, z0 - 1, hy);
    hRing[((z0 + 1) % 3) * 256] = ldsq(hk, z0,     hy);

    float accB[2] = {0,0}, accA[2] = {0,0}, accC[2] = {0,0};
    float j2 = 0.f;

    for (int zi = 0; zi < 16; zi++) {
        const int z = z0 + zi;
        const int slot = z & 1;
        const int so = slot * SLOT_F4;
        const bool zOK = (z + 1 < 128);

        // ---- loads first (latency covered by build+consume below) ----
        float4 hv = make_float4(0.f,0.f,0.f,0.f);
        if (zOK & hyOK) hv = sq4(*pHal);
        pHal += 4096;
        m2[0] = zOK ? sq4(*pOwn0) : make_float4(0.f,0.f,0.f,0.f);
        m2[1] = zOK ? sq4(*pOwn1) : make_float4(0.f,0.f,0.f,0.f);
        pOwn0 += 4096; pOwn1 += 4096;
        const float4 img = *pImg; pImg += 4096;

        // ---- build plane z ----
        float4 zs1;
        zOwnS0[so] = add4(add4(m0[0], m1[0]), m2[0]);
        zs1 = add4(add4(m0[1], m1[1]), m2[1]);
        zOwnS1[so] = zs1;
        hRing[((z + 2) % 3) * 256] = hv;   // raw ring slot for plane z+1
        zHalS[so] = add4(add4(hRing[0], hRing[256]), hRing[512]);
        if (tk != slot)
            exMine[slot * 128] = add4(m1[0], m1[1]);
        __syncthreads();

        // ---- consume plane z ----
        float4 jv;
        #pragma unroll
        for (int j = 0; j < 2; j++) {
            const float4 mc = m1[j];
            accB[j] += (mc.x + mc.y) + (mc.z + mc.w);
            float tX = mc.x*img.x, tY = mc.y*img.y, tZ = mc.z*img.z, tW = mc.w*img.w;
            accA[j] += (tX + tY) + (tZ + tW);
            accC[j] += fmaf(tX, img.x, fmaf(tY, img.y, fmaf(tZ, img.z, tW*img.w)));
        }
        const float4 a0 = xsum(m1[0]);
        {
            float4 b1 = add4(add4(zLoc[so], zs1), zLoc[so + 64]);
            jv.x = fmaf(a0.x, b1.x, -m1[0].x * m1[1].x);
            jv.y = fmaf(a0.y, b1.y, -m1[0].y * m1[1].y);
            jv.z = fmaf(a0.z, b1.z, -m1[0].z * m1[1].z);
            jv.w = fmaf(a0.w, b1.w, -m1[0].w * m1[1].w);
        }
        if (tk == slot) {
            float4 bO = add4(add4(add4(zOth0[so], zOth1[so]),
                                  add4(zOth0[so + 32], zOth1[so + 32])),
                             add4(zOth0[so + 64], zOth1[so + 64]));
            float4 aS = add4(a0, xsum(m1[1]));
            float4 cS = add4(m1[0], m1[1]);
            float4 cO = s_ex[slot*128 + ty*32 + tx];
            jv.x = fmaf(aS.x, bO.x, fmaf(-cS.x, cO.x, jv.x));
            jv.y = fmaf(aS.y, bO.y, fmaf(-cS.y, cO.y, jv.y));
            jv.z = fmaf(aS.z, bO.z, fmaf(-cS.z, cO.z, jv.z));
            jv.w = fmaf(aS.w, bO.w, fmaf(-cS.w, cO.w, jv.w));
        }
        j2 += (jv.x + jv.y) + (jv.z + jv.w);

        m0[0] = m1[0]; m0[1] = m1[1];
        m1[0] = m2[0]; m1[1] = m2[1];
    }

    // ---- reduction (J2 carries symmetry factor 2) ----
    float vals[7] = { accB[0], accB[1], accA[0], accA[1], accC[0], accC[1], 2.f * j2 };
    #pragma unroll
    for (int q = 0; q < 7; q++) {
        float v = vals[q];
        #pragma unroll
        for (int off = 16; off; off >>= 1) v += __shfl_xor_sync(FULLMASK, v, off);
        vals[q] = v;
    }
    __syncthreads();
    if (tx == 0) {
        #pragma unroll
        for (int q = 0; q < 7; q++) s_red[wid*8 + q] = vals[q];
    }
    __syncthreads();
    if (tid < 14) {
        const int g = tid / 7, q = tid % 7;
        float s = 0.f;
        #pragma unroll
        for (int w = 0; w < 4; w++) s += s_red[(4*g + w)*8 + q];
        double* dst;
        if (q < 2)       dst = &g_acc[b*4 + 2*g + q];
        else if (q < 4)  dst = &g_acc[8 + b*4 + 2*g + (q - 2)];
        else if (q < 6)  dst = &g_acc[16 + b*4 + 2*g + (q - 4)];
        else             dst = &g_acc[24];
        atomicAdd(dst, (double)s);
        __threadfence();
    }
    __syncthreads();

    // ---- last of 512 blocks finalizes + resets for next graph replay ----
    if (tid == 0) {
        unsigned old = atomicAdd(&g_sem, 1u);
        if (old == 511u) {
            volatile double* ga = g_acc;
            double j1 = 0.0;
            #pragma unroll
            for (int i = 0; i < 8; i++) {
                double Bv = ga[i], Av = ga[8 + i], Cv = ga[16 + i];
                j1 += Cv - Av * Av / Bv;
            }
            const double inv = 1.0 / 4194304.0;
            out[0] = (float)(j1 * inv + 0.0008 * ga[24] * inv);
            #pragma unroll
            for (int i = 0; i < 25; i++) g_acc[i] = 0.0;
            g_sem = 0u;
        }
    }
}

extern "C" void kernel_launch(void* const* d_in, const int* in_sizes, int n_in,
                              void* d_out, int out_size) {
    const float* ypred = (const float*)d_in[0];
    const float* image = (const float*)d_in[1];
    if (n_in >= 2 && in_sizes[0] < in_sizes[1]) {  // robustness to input order
        ypred = (const float*)d_in[1];
        image = (const float*)d_in[0];
    }
    cudaFuncSetAttribute(rfcm_kernel, cudaFuncAttributeMaxDynamicSharedMemorySize,
                         SMEM_BYTES);
    rfcm_kernel<<<dim3(32, 8, 2), dim3(32, 4, 2), SMEM_BYTES>>>(ypred, image, (float*)d_out);
}